// round 1
// baseline (speedup 1.0000x reference)
#include <cuda_runtime.h>
#include <math.h>

#define BATCH 8
#define CCH   256
#define NPOS  4096
#define SZ    (BATCH * CCH * NPOS)   // 8,388,608 floats

// Scratch: Q, K, V, ATT, AV (SZ each) + H (2*SZ) + scale/shift (1024)
__device__ float g_scratch[7ull * SZ + 1024];

// ---------------------------------------------------------------------------
// Generic 1x1 conv: y[b,o,n] = bias[o] + sum_c w[o,c] * x[b,c,n]
// grid (Npos/64, Cout/64, B), block 256. 64x64 tile, BK=32, 4x4 per thread.
// ---------------------------------------------------------------------------
__global__ __launch_bounds__(256) void conv1x1_kernel(
    const float* __restrict__ x, const float* __restrict__ w,
    const float* __restrict__ bias, float* __restrict__ y,
    int Cout, int Cin, int Npos)
{
    __shared__ float Ws[32][68];   // [k][o]
    __shared__ float Xs[32][64];   // [k][n]
    const int b  = blockIdx.z;
    const int ob = blockIdx.y * 64;
    const int nb = blockIdx.x * 64;
    const int tid = threadIdx.x;
    const int tx = tid & 15, ty = tid >> 4;
    const int n0 = tx * 4, o0 = ty * 4;
    float acc[4][4] = {};
    const float* xb = x + (size_t)b * Cin * Npos;
    for (int k0 = 0; k0 < Cin; k0 += 32) {
        {
            int o  = tid >> 2;
            int kk = (tid & 3) * 8;
            const float* wp = w + (size_t)(ob + o) * Cin + k0 + kk;
            #pragma unroll
            for (int i = 0; i < 8; ++i) Ws[kk + i][o] = wp[i];
        }
        #pragma unroll
        for (int i = 0; i < 8; ++i) {
            int idx = tid + i * 256;
            int k = idx >> 6, n = idx & 63;
            Xs[k][n] = xb[(size_t)(k0 + k) * Npos + nb + n];
        }
        __syncthreads();
        #pragma unroll
        for (int k = 0; k < 32; ++k) {
            float4 a  = *reinterpret_cast<const float4*>(&Ws[k][o0]);
            float4 xv = *reinterpret_cast<const float4*>(&Xs[k][n0]);
            acc[0][0] += a.x*xv.x; acc[0][1] += a.x*xv.y; acc[0][2] += a.x*xv.z; acc[0][3] += a.x*xv.w;
            acc[1][0] += a.y*xv.x; acc[1][1] += a.y*xv.y; acc[1][2] += a.y*xv.z; acc[1][3] += a.y*xv.w;
            acc[2][0] += a.z*xv.x; acc[2][1] += a.z*xv.y; acc[2][2] += a.z*xv.z; acc[2][3] += a.z*xv.w;
            acc[3][0] += a.w*xv.x; acc[3][1] += a.w*xv.y; acc[3][2] += a.w*xv.z; acc[3][3] += a.w*xv.w;
        }
        __syncthreads();
    }
    #pragma unroll
    for (int oi = 0; oi < 4; ++oi) {
        float bb = bias[ob + o0 + oi];
        float4 r = make_float4(acc[oi][0]+bb, acc[oi][1]+bb, acc[oi][2]+bb, acc[oi][3]+bb);
        *reinterpret_cast<float4*>(&y[((size_t)b * Cout + ob + o0 + oi) * Npos + nb + n0]) = r;
    }
}

// ---------------------------------------------------------------------------
// conv1x1 on concat([x1 (256ch), x2 (256ch)]) -> 512 out channels
// ---------------------------------------------------------------------------
__global__ __launch_bounds__(256) void conv1x1_cat_kernel(
    const float* __restrict__ x1, const float* __restrict__ x2,
    const float* __restrict__ w, const float* __restrict__ bias,
    float* __restrict__ y)
{
    __shared__ float Ws[32][68];
    __shared__ float Xs[32][64];
    const int b  = blockIdx.z;
    const int ob = blockIdx.y * 64;
    const int nb = blockIdx.x * 64;
    const int tid = threadIdx.x;
    const int tx = tid & 15, ty = tid >> 4;
    const int n0 = tx * 4, o0 = ty * 4;
    float acc[4][4] = {};
    for (int k0 = 0; k0 < 512; k0 += 32) {
        const float* xb = (k0 < 256)
            ? x1 + ((size_t)b * 256 + k0) * NPOS
            : x2 + ((size_t)b * 256 + (k0 - 256)) * NPOS;
        {
            int o  = tid >> 2;
            int kk = (tid & 3) * 8;
            const float* wp = w + (size_t)(ob + o) * 512 + k0 + kk;
            #pragma unroll
            for (int i = 0; i < 8; ++i) Ws[kk + i][o] = wp[i];
        }
        #pragma unroll
        for (int i = 0; i < 8; ++i) {
            int idx = tid + i * 256;
            int k = idx >> 6, n = idx & 63;
            Xs[k][n] = xb[(size_t)k * NPOS + nb + n];
        }
        __syncthreads();
        #pragma unroll
        for (int k = 0; k < 32; ++k) {
            float4 a  = *reinterpret_cast<const float4*>(&Ws[k][o0]);
            float4 xv = *reinterpret_cast<const float4*>(&Xs[k][n0]);
            acc[0][0] += a.x*xv.x; acc[0][1] += a.x*xv.y; acc[0][2] += a.x*xv.z; acc[0][3] += a.x*xv.w;
            acc[1][0] += a.y*xv.x; acc[1][1] += a.y*xv.y; acc[1][2] += a.y*xv.z; acc[1][3] += a.y*xv.w;
            acc[2][0] += a.z*xv.x; acc[2][1] += a.z*xv.y; acc[2][2] += a.z*xv.z; acc[2][3] += a.z*xv.w;
            acc[3][0] += a.w*xv.x; acc[3][1] += a.w*xv.y; acc[3][2] += a.w*xv.z; acc[3][3] += a.w*xv.w;
        }
        __syncthreads();
    }
    #pragma unroll
    for (int oi = 0; oi < 4; ++oi) {
        float bb = bias[ob + o0 + oi];
        float4 r = make_float4(acc[oi][0]+bb, acc[oi][1]+bb, acc[oi][2]+bb, acc[oi][3]+bb);
        *reinterpret_cast<float4*>(&y[((size_t)b * 512 + ob + o0 + oi) * NPOS + nb + n0]) = r;
    }
}

// ---------------------------------------------------------------------------
// BN stats: per-channel mean/var over (B, N); writes fused scale/shift
// ---------------------------------------------------------------------------
__global__ __launch_bounds__(256) void bn_stats_kernel(
    const float* __restrict__ h, const float* __restrict__ gamma,
    const float* __restrict__ beta, float* __restrict__ scale,
    float* __restrict__ shift)
{
    const int ch = blockIdx.x;   // 0..511
    const int tid = threadIdx.x;
    float s = 0.f, s2 = 0.f;
    for (int b = 0; b < BATCH; ++b) {
        const float4* p = reinterpret_cast<const float4*>(h + ((size_t)b * 512 + ch) * NPOS);
        for (int i = tid; i < NPOS / 4; i += 256) {
            float4 v = p[i];
            s  += (v.x + v.y) + (v.z + v.w);
            s2 += v.x*v.x + v.y*v.y + v.z*v.z + v.w*v.w;
        }
    }
    __shared__ float r1[256], r2[256];
    r1[tid] = s; r2[tid] = s2;
    __syncthreads();
    for (int off = 128; off > 0; off >>= 1) {
        if (tid < off) { r1[tid] += r1[tid + off]; r2[tid] += r2[tid + off]; }
        __syncthreads();
    }
    if (tid == 0) {
        const float inv = 1.f / (float)(BATCH * NPOS);
        float mean = r1[0] * inv;
        float var  = r2[0] * inv - mean * mean;
        float rs   = rsqrtf(var + 1e-5f);
        float scv  = gamma[ch] * rs;
        scale[ch] = scv;
        shift[ch] = beta[ch] - mean * scv;
    }
}

// ---------------------------------------------------------------------------
// Final conv1x1 over BN+ReLU-transformed h, plus bias and residual.
// ---------------------------------------------------------------------------
__global__ __launch_bounds__(256) void conv1x1_bnout_kernel(
    const float* __restrict__ h, const float* __restrict__ scale,
    const float* __restrict__ shift, const float* __restrict__ w,
    const float* __restrict__ bias, const float* __restrict__ resid,
    float* __restrict__ y)
{
    __shared__ float Ws[32][68];
    __shared__ float Xs[32][64];
    const int b  = blockIdx.z;
    const int ob = blockIdx.y * 64;
    const int nb = blockIdx.x * 64;
    const int tid = threadIdx.x;
    const int tx = tid & 15, ty = tid >> 4;
    const int n0 = tx * 4, o0 = ty * 4;
    float acc[4][4] = {};
    for (int k0 = 0; k0 < 512; k0 += 32) {
        const float* xb = h + ((size_t)b * 512 + k0) * NPOS;
        {
            int o  = tid >> 2;
            int kk = (tid & 3) * 8;
            const float* wp = w + (size_t)(ob + o) * 512 + k0 + kk;
            #pragma unroll
            for (int i = 0; i < 8; ++i) Ws[kk + i][o] = wp[i];
        }
        #pragma unroll
        for (int i = 0; i < 8; ++i) {
            int idx = tid + i * 256;
            int k = idx >> 6, n = idx & 63;
            float v = xb[(size_t)k * NPOS + nb + n];
            v = fmaf(v, __ldg(&scale[k0 + k]), __ldg(&shift[k0 + k]));
            Xs[k][n] = fmaxf(v, 0.f);
        }
        __syncthreads();
        #pragma unroll
        for (int k = 0; k < 32; ++k) {
            float4 a  = *reinterpret_cast<const float4*>(&Ws[k][o0]);
            float4 xv = *reinterpret_cast<const float4*>(&Xs[k][n0]);
            acc[0][0] += a.x*xv.x; acc[0][1] += a.x*xv.y; acc[0][2] += a.x*xv.z; acc[0][3] += a.x*xv.w;
            acc[1][0] += a.y*xv.x; acc[1][1] += a.y*xv.y; acc[1][2] += a.y*xv.z; acc[1][3] += a.y*xv.w;
            acc[2][0] += a.z*xv.x; acc[2][1] += a.z*xv.y; acc[2][2] += a.z*xv.z; acc[2][3] += a.z*xv.w;
            acc[3][0] += a.w*xv.x; acc[3][1] += a.w*xv.y; acc[3][2] += a.w*xv.z; acc[3][3] += a.w*xv.w;
        }
        __syncthreads();
    }
    #pragma unroll
    for (int oi = 0; oi < 4; ++oi) {
        float bb = bias[ob + o0 + oi];
        const float4 rv = *reinterpret_cast<const float4*>(
            &resid[((size_t)b * 256 + ob + o0 + oi) * NPOS + nb + n0]);
        float4 r = make_float4(acc[oi][0]+bb+rv.x, acc[oi][1]+bb+rv.y,
                               acc[oi][2]+bb+rv.z, acc[oi][3]+bb+rv.w);
        *reinterpret_cast<float4*>(&y[((size_t)b * 256 + ob + o0 + oi) * NPOS + nb + n0]) = r;
    }
}

// ---------------------------------------------------------------------------
// Flash attention: per (b,h) head, D=64, online softmax over M=4096.
// Tiles: 64 n-rows per block, 64 m per iteration. grid (N/64, HEAD, B).
// ---------------------------------------------------------------------------
#define FLASH_SMEM_FLOATS (4096 + 4096 + 4352 + 4352 + 192)

__global__ __launch_bounds__(256) void flash_attn_kernel(
    const float* __restrict__ Q, const float* __restrict__ K,
    const float* __restrict__ V, float* __restrict__ O)
{
    extern __shared__ float sm[];
    float* qs  = sm;                       // [64][64]  (d, n)
    float* ks  = sm + 4096;                // [64][64]  (d, m)
    float* vst = sm + 8192;                // [64][68]  (m, d)
    float* ps  = sm + 8192 + 4352;         // [64][68]  (m, n)
    float* mi  = ps + 4352;                // [64]
    float* li  = mi + 64;                  // [64]
    float* al  = li + 64;                  // [64]

    const int b  = blockIdx.z;
    const int hh = blockIdx.y;
    const int nb = blockIdx.x * 64;
    const int tid = threadIdx.x;
    const int tx = tid & 15, ty = tid >> 4;
    const int n0 = tx * 4;
    const int c0 = ty * 4;                 // m-offset in phase A, d-offset in phase C

    const size_t headoff = ((size_t)b * CCH + hh * 64) * NPOS;
    const float* Qh = Q + headoff;
    const float* Kh = K + headoff;
    const float* Vh = V + headoff;

    #pragma unroll
    for (int i = 0; i < 16; ++i) {
        int idx = tid + i * 256;
        int d = idx >> 6, n = idx & 63;
        qs[d * 64 + n] = Qh[(size_t)d * NPOS + nb + n];
    }
    if (tid < 64) { mi[tid] = -1e30f; li[tid] = 0.f; }
    float oacc[4][4] = {};                 // [ni][di]
    __syncthreads();

    const int row = tid >> 2, lane = tid & 3;

    for (int mb = 0; mb < NPOS; mb += 64) {
        // load K (d,m) and V transposed (m,d)
        #pragma unroll
        for (int i = 0; i < 16; ++i) {
            int idx = tid + i * 256;
            int d = idx >> 6, m = idx & 63;
            ks[d * 64 + m]  = Kh[(size_t)d * NPOS + mb + m];
            vst[m * 68 + d] = Vh[(size_t)d * NPOS + mb + m];
        }
        __syncthreads();

        // Phase A: s[mj][ni] = sum_d q[d][n]*k[d][m]
        float s[4][4] = {};
        #pragma unroll
        for (int d = 0; d < 64; ++d) {
            float4 a  = *reinterpret_cast<const float4*>(&qs[d * 64 + n0]);
            float4 kv = *reinterpret_cast<const float4*>(&ks[d * 64 + c0]);
            s[0][0]+=kv.x*a.x; s[0][1]+=kv.x*a.y; s[0][2]+=kv.x*a.z; s[0][3]+=kv.x*a.w;
            s[1][0]+=kv.y*a.x; s[1][1]+=kv.y*a.y; s[1][2]+=kv.y*a.z; s[1][3]+=kv.y*a.w;
            s[2][0]+=kv.z*a.x; s[2][1]+=kv.z*a.y; s[2][2]+=kv.z*a.z; s[2][3]+=kv.z*a.w;
            s[3][0]+=kv.w*a.x; s[3][1]+=kv.w*a.y; s[3][2]+=kv.w*a.z; s[3][3]+=kv.w*a.w;
        }
        #pragma unroll
        for (int mj = 0; mj < 4; ++mj) {
            float4 r = make_float4(s[mj][0]*0.125f, s[mj][1]*0.125f,
                                   s[mj][2]*0.125f, s[mj][3]*0.125f);
            *reinterpret_cast<float4*>(&ps[(c0 + mj) * 68 + n0]) = r;
        }
        __syncthreads();

        // Phase B: online softmax per row (4 lanes per row)
        {
            float vmax = -1e30f;
            #pragma unroll
            for (int j = 0; j < 16; ++j)
                vmax = fmaxf(vmax, ps[(lane + 4*j) * 68 + row]);
            vmax = fmaxf(vmax, __shfl_xor_sync(0xffffffffu, vmax, 1));
            vmax = fmaxf(vmax, __shfl_xor_sync(0xffffffffu, vmax, 2));
            float old = mi[row];
            float nm  = fmaxf(old, vmax);
            float a   = __expf(old - nm);
            float psum = 0.f;
            #pragma unroll
            for (int j = 0; j < 16; ++j) {
                int m = lane + 4*j;
                float p = __expf(ps[m * 68 + row] - nm);
                ps[m * 68 + row] = p;
                psum += p;
            }
            psum += __shfl_xor_sync(0xffffffffu, psum, 1);
            psum += __shfl_xor_sync(0xffffffffu, psum, 2);
            if (lane == 0) {
                mi[row] = nm;
                li[row] = li[row] * a + psum;
                al[row] = a;
            }
        }
        __syncthreads();

        // Phase C: o[ni][di] = o*alpha + sum_m p[m][n]*v[m][d]
        {
            float a0 = al[n0], a1 = al[n0+1], a2 = al[n0+2], a3 = al[n0+3];
            #pragma unroll
            for (int di = 0; di < 4; ++di) {
                oacc[0][di]*=a0; oacc[1][di]*=a1; oacc[2][di]*=a2; oacc[3][di]*=a3;
            }
            #pragma unroll
            for (int m = 0; m < 64; ++m) {
                float4 p  = *reinterpret_cast<const float4*>(&ps[m * 68 + n0]);
                float4 vv = *reinterpret_cast<const float4*>(&vst[m * 68 + c0]);
                oacc[0][0]+=p.x*vv.x; oacc[0][1]+=p.x*vv.y; oacc[0][2]+=p.x*vv.z; oacc[0][3]+=p.x*vv.w;
                oacc[1][0]+=p.y*vv.x; oacc[1][1]+=p.y*vv.y; oacc[1][2]+=p.y*vv.z; oacc[1][3]+=p.y*vv.w;
                oacc[2][0]+=p.z*vv.x; oacc[2][1]+=p.z*vv.y; oacc[2][2]+=p.z*vv.z; oacc[2][3]+=p.z*vv.w;
                oacc[3][0]+=p.w*vv.x; oacc[3][1]+=p.w*vv.y; oacc[3][2]+=p.w*vv.z; oacc[3][3]+=p.w*vv.w;
            }
        }
        __syncthreads();
    }

    const float i0 = 1.f/li[n0],   i1 = 1.f/li[n0+1];
    const float i2 = 1.f/li[n0+2], i3 = 1.f/li[n0+3];
    #pragma unroll
    for (int di = 0; di < 4; ++di) {
        float4 r = make_float4(oacc[0][di]*i0, oacc[1][di]*i1,
                               oacc[2][di]*i2, oacc[3][di]*i3);
        *reinterpret_cast<float4*>(&O[headoff + (size_t)(c0 + di) * NPOS + nb + n0]) = r;
    }
}

// ---------------------------------------------------------------------------
extern "C" void kernel_launch(void* const* d_in, const int* in_sizes, int n_in,
                              void* d_out, int out_size)
{
    const float* m1    = (const float*)d_in[0];
    const float* m2    = (const float*)d_in[1];
    const float* wq    = (const float*)d_in[2];
    const float* bq    = (const float*)d_in[3];
    const float* wk    = (const float*)d_in[4];
    const float* bk    = (const float*)d_in[5];
    const float* wv    = (const float*)d_in[6];
    const float* bv    = (const float*)d_in[7];
    const float* wm    = (const float*)d_in[8];
    const float* bm    = (const float*)d_in[9];
    const float* w1    = (const float*)d_in[10];
    const float* b1    = (const float*)d_in[11];
    const float* gamma = (const float*)d_in[12];
    const float* beta  = (const float*)d_in[13];
    const float* w2    = (const float*)d_in[14];
    const float* b2    = (const float*)d_in[15];
    float* out = (float*)d_out;

    float* base = nullptr;
    cudaGetSymbolAddress((void**)&base, g_scratch);
    float* Q     = base;
    float* K     = base + (size_t)SZ;
    float* V     = base + 2*(size_t)SZ;
    float* ATT   = base + 3*(size_t)SZ;
    float* AV    = base + 4*(size_t)SZ;
    float* H     = base + 5*(size_t)SZ;      // 2*SZ floats
    float* SCALE = base + 7*(size_t)SZ;
    float* SHIFT = SCALE + 512;

    const int flash_smem = FLASH_SMEM_FLOATS * (int)sizeof(float);
    cudaFuncSetAttribute(flash_attn_kernel,
                         cudaFuncAttributeMaxDynamicSharedMemorySize, flash_smem);

    dim3 blk(256);
    conv1x1_kernel<<<dim3(64, 4, 8), blk>>>(m1, wq, bq, Q, 256, 256, NPOS);
    conv1x1_kernel<<<dim3(64, 4, 8), blk>>>(m2, wk, bk, K, 256, 256, NPOS);
    conv1x1_kernel<<<dim3(64, 4, 8), blk>>>(m2, wv, bv, V, 256, 256, NPOS);
    flash_attn_kernel<<<dim3(64, 4, 8), blk, flash_smem>>>(Q, K, V, ATT);
    conv1x1_kernel<<<dim3(64, 4, 8), blk>>>(ATT, wm, bm, AV, 256, 256, NPOS);
    conv1x1_cat_kernel<<<dim3(64, 8, 8), blk>>>(m1, AV, w1, b1, H);
    bn_stats_kernel<<<512, blk>>>(H, gamma, beta, SCALE, SHIFT);
    conv1x1_bnout_kernel<<<dim3(64, 4, 8), blk>>>(H, SCALE, SHIFT, w2, b2, m1, out);
}

// round 3
// speedup vs baseline: 2.5542x; 2.5542x over previous
#include <cuda_runtime.h>
#include <cuda_bf16.h>
#include <math.h>
#include <stdint.h>

#define BATCH 8
#define CCH   256
#define NPOS  4096
#define SZ    (BATCH * CCH * NPOS)   // 8,388,608

// Scratch (floats): Qb,Kb,Vb bf16 (1.5 SZ) + O (1) + AV (1) + H (2) + scale/shift
__device__ float g_scratch[7ull * SZ + 1024];

// ---------------------------------------------------------------------------
// helpers
// ---------------------------------------------------------------------------
__device__ __forceinline__ float fast_exp2(float x) {
    x = fmaxf(x, -126.0f);
    float t = x + 12582912.0f;                 // round-to-nearest-int magic
    int   i = __float_as_int(t) - 0x4B400000;  // integer part
    float f = x - (t - 12582912.0f);           // frac in [-0.5, 0.5]
    float p =             1.3333558e-3f;
    p = fmaf(p, f, 9.6181291e-3f);
    p = fmaf(p, f, 5.5504109e-2f);
    p = fmaf(p, f, 2.4022651e-1f);
    p = fmaf(p, f, 6.9314718e-1f);
    p = fmaf(p, f, 1.0f);
    return __int_as_float(__float_as_int(p) + (i << 23));
}

__device__ __forceinline__ uint32_t packbf(float lo, float hi) {
    __nv_bfloat162 v = __floats2bfloat162_rn(lo, hi);
    return *reinterpret_cast<uint32_t*>(&v);
}

__device__ __forceinline__ void ldsm4(uint32_t& r0, uint32_t& r1, uint32_t& r2,
                                      uint32_t& r3, uint32_t a) {
    asm volatile("ldmatrix.sync.aligned.m8n8.x4.shared.b16 {%0,%1,%2,%3}, [%4];\n"
                 : "=r"(r0), "=r"(r1), "=r"(r2), "=r"(r3) : "r"(a));
}
__device__ __forceinline__ void ldsm4t(uint32_t& r0, uint32_t& r1, uint32_t& r2,
                                       uint32_t& r3, uint32_t a) {
    asm volatile("ldmatrix.sync.aligned.m8n8.x4.trans.shared.b16 {%0,%1,%2,%3}, [%4];\n"
                 : "=r"(r0), "=r"(r1), "=r"(r2), "=r"(r3) : "r"(a));
}
__device__ __forceinline__ void mma16816(float* d, const uint32_t* a,
                                         uint32_t b0, uint32_t b1) {
    asm volatile("mma.sync.aligned.m16n8k16.row.col.f32.bf16.bf16.f32 "
                 "{%0,%1,%2,%3}, {%4,%5,%6,%7}, {%8,%9}, {%0,%1,%2,%3};\n"
                 : "+f"(d[0]), "+f"(d[1]), "+f"(d[2]), "+f"(d[3])
                 : "r"(a[0]), "r"(a[1]), "r"(a[2]), "r"(a[3]), "r"(b0), "r"(b1));
}
// swizzled smem byte offset: 64 bf16 per row (128B), 16B chunks XOR row%8
__device__ __forceinline__ uint32_t swz(uint32_t row, uint32_t chunk) {
    return row * 128u + ((chunk ^ (row & 7u)) * 16u);
}

// ---------------------------------------------------------------------------
// Generic fp32 1x1 conv (unchanged from R1)
// ---------------------------------------------------------------------------
__global__ __launch_bounds__(256) void conv1x1_kernel(
    const float* __restrict__ x, const float* __restrict__ w,
    const float* __restrict__ bias, float* __restrict__ y,
    int Cout, int Cin, int Npos)
{
    __shared__ float Ws[32][68];
    __shared__ float Xs[32][64];
    const int b  = blockIdx.z;
    const int ob = blockIdx.y * 64;
    const int nb = blockIdx.x * 64;
    const int tid = threadIdx.x;
    const int tx = tid & 15, ty = tid >> 4;
    const int n0 = tx * 4, o0 = ty * 4;
    float acc[4][4] = {};
    const float* xb = x + (size_t)b * Cin * Npos;
    for (int k0 = 0; k0 < Cin; k0 += 32) {
        {
            int o  = tid >> 2;
            int kk = (tid & 3) * 8;
            const float* wp = w + (size_t)(ob + o) * Cin + k0 + kk;
            #pragma unroll
            for (int i = 0; i < 8; ++i) Ws[kk + i][o] = wp[i];
        }
        #pragma unroll
        for (int i = 0; i < 8; ++i) {
            int idx = tid + i * 256;
            int k = idx >> 6, n = idx & 63;
            Xs[k][n] = xb[(size_t)(k0 + k) * Npos + nb + n];
        }
        __syncthreads();
        #pragma unroll
        for (int k = 0; k < 32; ++k) {
            float4 a  = *reinterpret_cast<const float4*>(&Ws[k][o0]);
            float4 xv = *reinterpret_cast<const float4*>(&Xs[k][n0]);
            acc[0][0] += a.x*xv.x; acc[0][1] += a.x*xv.y; acc[0][2] += a.x*xv.z; acc[0][3] += a.x*xv.w;
            acc[1][0] += a.y*xv.x; acc[1][1] += a.y*xv.y; acc[1][2] += a.y*xv.z; acc[1][3] += a.y*xv.w;
            acc[2][0] += a.z*xv.x; acc[2][1] += a.z*xv.y; acc[2][2] += a.z*xv.z; acc[2][3] += a.z*xv.w;
            acc[3][0] += a.w*xv.x; acc[3][1] += a.w*xv.y; acc[3][2] += a.w*xv.z; acc[3][3] += a.w*xv.w;
        }
        __syncthreads();
    }
    #pragma unroll
    for (int oi = 0; oi < 4; ++oi) {
        float bb = bias[ob + o0 + oi];
        float4 r = make_float4(acc[oi][0]+bb, acc[oi][1]+bb, acc[oi][2]+bb, acc[oi][3]+bb);
        *reinterpret_cast<float4*>(&y[((size_t)b * Cout + ob + o0 + oi) * Npos + nb + n0]) = r;
    }
}

// ---------------------------------------------------------------------------
// QKV conv: fp32 GEMM, writes bf16 in [b, h, n, d] layout, optional scale.
// grid (64, 4, 8): blockIdx.y = head (64 output channels per head).
// ---------------------------------------------------------------------------
__global__ __launch_bounds__(256) void conv1x1_qkv_bf16(
    const float* __restrict__ x, const float* __restrict__ w,
    const float* __restrict__ bias, __nv_bfloat16* __restrict__ y,
    float outscale)
{
    __shared__ float Ws[32][68];
    __shared__ float Xs[32][64];
    const int b  = blockIdx.z;
    const int h  = blockIdx.y;
    const int ob = h * 64;
    const int nb = blockIdx.x * 64;
    const int tid = threadIdx.x;
    const int tx = tid & 15, ty = tid >> 4;
    const int n0 = tx * 4, o0 = ty * 4;
    float acc[4][4] = {};
    const float* xb = x + (size_t)b * 256 * NPOS;
    for (int k0 = 0; k0 < 256; k0 += 32) {
        {
            int o  = tid >> 2;
            int kk = (tid & 3) * 8;
            const float* wp = w + (size_t)(ob + o) * 256 + k0 + kk;
            #pragma unroll
            for (int i = 0; i < 8; ++i) Ws[kk + i][o] = wp[i];
        }
        #pragma unroll
        for (int i = 0; i < 8; ++i) {
            int idx = tid + i * 256;
            int k = idx >> 6, n = idx & 63;
            Xs[k][n] = xb[(size_t)(k0 + k) * NPOS + nb + n];
        }
        __syncthreads();
        #pragma unroll
        for (int k = 0; k < 32; ++k) {
            float4 a  = *reinterpret_cast<const float4*>(&Ws[k][o0]);
            float4 xv = *reinterpret_cast<const float4*>(&Xs[k][n0]);
            acc[0][0] += a.x*xv.x; acc[0][1] += a.x*xv.y; acc[0][2] += a.x*xv.z; acc[0][3] += a.x*xv.w;
            acc[1][0] += a.y*xv.x; acc[1][1] += a.y*xv.y; acc[1][2] += a.y*xv.z; acc[1][3] += a.y*xv.w;
            acc[2][0] += a.z*xv.x; acc[2][1] += a.z*xv.y; acc[2][2] += a.z*xv.z; acc[2][3] += a.z*xv.w;
            acc[3][0] += a.w*xv.x; acc[3][1] += a.w*xv.y; acc[3][2] += a.w*xv.z; acc[3][3] += a.w*xv.w;
        }
        __syncthreads();
    }
    const float b0v = bias[ob + o0 + 0], b1v = bias[ob + o0 + 1];
    const float b2v = bias[ob + o0 + 2], b3v = bias[ob + o0 + 3];
    #pragma unroll
    for (int ni = 0; ni < 4; ++ni) {
        float v0 = (acc[0][ni] + b0v) * outscale;
        float v1 = (acc[1][ni] + b1v) * outscale;
        float v2 = (acc[2][ni] + b2v) * outscale;
        float v3 = (acc[3][ni] + b3v) * outscale;
        uint2 pp;
        pp.x = packbf(v0, v1);
        pp.y = packbf(v2, v3);
        *reinterpret_cast<uint2*>(
            &y[(((size_t)(b * 4 + h)) * NPOS + nb + n0 + ni) * 64 + o0]) = pp;
    }
}

// ---------------------------------------------------------------------------
// Flash attention, bf16 mma.sync, flash-2 online softmax (exp2 poly, no MUFU).
// Q pre-scaled by 0.125*log2(e). Block: 256 thr (8 warps), q-tile 128, kv 64.
// grid (32, 4, 8). dyn smem = 48KB: Qs 16K + 2 stages x (Ks 8K + Vs 8K).
// ---------------------------------------------------------------------------
__global__ __launch_bounds__(256, 2) void flash_mma_kernel(
    const __nv_bfloat16* __restrict__ Qb, const __nv_bfloat16* __restrict__ Kb,
    const __nv_bfloat16* __restrict__ Vb, float* __restrict__ O)
{
    extern __shared__ char smc[];
    const int tid = threadIdx.x;
    const int w = tid >> 5, l = tid & 31;
    const int b = blockIdx.z, h = blockIdx.y;
    const int nb = blockIdx.x * 128;
    const size_t headbase = ((size_t)(b * 4 + h)) * NPOS * 64;

    const uint32_t smem_base = (uint32_t)__cvta_generic_to_shared(smc);
    const uint32_t qs_b = smem_base;

    // load Q tile (128 x 64 bf16), swizzled
    #pragma unroll
    for (int i = 0; i < 4; ++i) {
        int idx = tid + i * 256;
        int r = idx >> 3, c = idx & 7;
        const int4* src = reinterpret_cast<const int4*>(
            Qb + headbase + (size_t)(nb + r) * 64 + c * 8);
        *reinterpret_cast<int4*>(smc + swz(r, c)) = *src;
    }

    // async K/V tile loader
    auto load_tile = [&](int mb, int s) {
        uint32_t kbase = smem_base + 16384 + s * 16384;
        uint32_t vbase = kbase + 8192;
        #pragma unroll
        for (int i = 0; i < 2; ++i) {
            int idx = tid + i * 256;
            int r = idx >> 3, c = idx & 7;
            const __nv_bfloat16* ksrc = Kb + headbase + (size_t)(mb + r) * 64 + c * 8;
            const __nv_bfloat16* vsrc = Vb + headbase + (size_t)(mb + r) * 64 + c * 8;
            uint32_t o = swz(r, c);
            asm volatile("cp.async.cg.shared.global [%0], [%1], 16;\n"
                         :: "r"(kbase + o), "l"(ksrc));
            asm volatile("cp.async.cg.shared.global [%0], [%1], 16;\n"
                         :: "r"(vbase + o), "l"(vsrc));
        }
        asm volatile("cp.async.commit_group;\n");
    };
    load_tile(0, 0);

    float oacc[8][4] = {};
    float mA = -10000.f, mB = -10000.f, lA = 0.f, lB = 0.f;
    const int m0q = w * 16;
    const uint32_t arow = m0q + (l & 15);     // A-frag/V-frag row pattern
    const uint32_t achk = (uint32_t)(l >> 4); // chunk +1 for lanes 16-31
    const uint32_t brow8 = (l & 7) + ((l & 16) >> 1); // S-phase B rows
    const uint32_t bchk = (uint32_t)((l >> 3) & 1);

    for (int it = 0; it < NPOS / 64; ++it) {
        if (it + 1 < NPOS / 64) {
            load_tile((it + 1) * 64, (it + 1) & 1);
            asm volatile("cp.async.wait_group 1;\n");
        } else {
            asm volatile("cp.async.wait_group 0;\n");
        }
        __syncthreads();
        const uint32_t kb = smem_base + 16384 + (it & 1) * 16384;
        const uint32_t vb = kb + 8192;

        // ---- S = Q K^T  (sacc[j][0..3]: n-block j, C-frag) ----
        float sacc[8][4] = {};
        #pragma unroll
        for (int kk = 0; kk < 4; ++kk) {
            uint32_t af[4];
            ldsm4(af[0], af[1], af[2], af[3], qs_b + swz(arow, kk * 2 + achk));
            #pragma unroll
            for (int jj = 0; jj < 4; ++jj) {
                uint32_t b0, b1, b2, b3;
                ldsm4(b0, b1, b2, b3, kb + swz(jj * 16 + brow8, kk * 2 + bchk));
                mma16816(sacc[2 * jj], af, b0, b1);
                mma16816(sacc[2 * jj + 1], af, b2, b3);
            }
        }

        // ---- online softmax (log2 domain) ----
        float rmA = -1e30f, rmB = -1e30f;
        #pragma unroll
        for (int j = 0; j < 8; ++j) {
            rmA = fmaxf(rmA, fmaxf(sacc[j][0], sacc[j][1]));
            rmB = fmaxf(rmB, fmaxf(sacc[j][2], sacc[j][3]));
        }
        rmA = fmaxf(rmA, __shfl_xor_sync(0xffffffffu, rmA, 1));
        rmA = fmaxf(rmA, __shfl_xor_sync(0xffffffffu, rmA, 2));
        rmB = fmaxf(rmB, __shfl_xor_sync(0xffffffffu, rmB, 1));
        rmB = fmaxf(rmB, __shfl_xor_sync(0xffffffffu, rmB, 2));
        const float mnA = fmaxf(mA, rmA), mnB = fmaxf(mB, rmB);
        const float aA = fast_exp2(mA - mnA), aB = fast_exp2(mB - mnB);
        mA = mnA; mB = mnB;
        float psA = 0.f, psB = 0.f;
        #pragma unroll
        for (int j = 0; j < 8; ++j) {
            sacc[j][0] = fast_exp2(sacc[j][0] - mnA);
            sacc[j][1] = fast_exp2(sacc[j][1] - mnA);
            sacc[j][2] = fast_exp2(sacc[j][2] - mnB);
            sacc[j][3] = fast_exp2(sacc[j][3] - mnB);
            psA += sacc[j][0] + sacc[j][1];
            psB += sacc[j][2] + sacc[j][3];
        }
        psA += __shfl_xor_sync(0xffffffffu, psA, 1);
        psA += __shfl_xor_sync(0xffffffffu, psA, 2);
        psB += __shfl_xor_sync(0xffffffffu, psB, 1);
        psB += __shfl_xor_sync(0xffffffffu, psB, 2);
        lA = lA * aA + psA;
        lB = lB * aB + psB;
        #pragma unroll
        for (int j = 0; j < 8; ++j) {
            oacc[j][0] *= aA; oacc[j][1] *= aA;
            oacc[j][2] *= aB; oacc[j][3] *= aB;
        }

        // ---- O += P V ----
        #pragma unroll
        for (int kk = 0; kk < 4; ++kk) {
            uint32_t pa[4];
            pa[0] = packbf(sacc[2*kk][0],   sacc[2*kk][1]);
            pa[1] = packbf(sacc[2*kk][2],   sacc[2*kk][3]);
            pa[2] = packbf(sacc[2*kk+1][0], sacc[2*kk+1][1]);
            pa[3] = packbf(sacc[2*kk+1][2], sacc[2*kk+1][3]);
            const uint32_t vrow = kk * 16 + (l & 15);
            #pragma unroll
            for (int jj = 0; jj < 4; ++jj) {
                uint32_t b0, b1, b2, b3;
                ldsm4t(b0, b1, b2, b3, vb + swz(vrow, jj * 2 + achk));
                mma16816(oacc[2 * jj], pa, b0, b1);
                mma16816(oacc[2 * jj + 1], pa, b2, b3);
            }
        }
        __syncthreads();
    }

    // ---- epilogue: normalize, write O fp32 [b, c, n] ----
    const float ilA = 1.f / lA, ilB = 1.f / lB;
    const int rA = nb + m0q + (l >> 2), rB = rA + 8;
    const size_t obase = ((size_t)b * CCH + h * 64) * NPOS;
    #pragma unroll
    for (int j = 0; j < 8; ++j) {
        int d0 = j * 8 + (l & 3) * 2;
        O[obase + (size_t)d0 * NPOS + rA]       = oacc[j][0] * ilA;
        O[obase + (size_t)(d0 + 1) * NPOS + rA] = oacc[j][1] * ilA;
        O[obase + (size_t)d0 * NPOS + rB]       = oacc[j][2] * ilB;
        O[obase + (size_t)(d0 + 1) * NPOS + rB] = oacc[j][3] * ilB;
    }
}

// ---------------------------------------------------------------------------
// conv1x1 on concat([x1, x2]) -> 512 channels (unchanged)
// ---------------------------------------------------------------------------
__global__ __launch_bounds__(256) void conv1x1_cat_kernel(
    const float* __restrict__ x1, const float* __restrict__ x2,
    const float* __restrict__ w, const float* __restrict__ bias,
    float* __restrict__ y)
{
    __shared__ float Ws[32][68];
    __shared__ float Xs[32][64];
    const int b  = blockIdx.z;
    const int ob = blockIdx.y * 64;
    const int nb = blockIdx.x * 64;
    const int tid = threadIdx.x;
    const int tx = tid & 15, ty = tid >> 4;
    const int n0 = tx * 4, o0 = ty * 4;
    float acc[4][4] = {};
    for (int k0 = 0; k0 < 512; k0 += 32) {
        const float* xb = (k0 < 256)
            ? x1 + ((size_t)b * 256 + k0) * NPOS
            : x2 + ((size_t)b * 256 + (k0 - 256)) * NPOS;
        {
            int o  = tid >> 2;
            int kk = (tid & 3) * 8;
            const float* wp = w + (size_t)(ob + o) * 512 + k0 + kk;
            #pragma unroll
            for (int i = 0; i < 8; ++i) Ws[kk + i][o] = wp[i];
        }
        #pragma unroll
        for (int i = 0; i < 8; ++i) {
            int idx = tid + i * 256;
            int k = idx >> 6, n = idx & 63;
            Xs[k][n] = xb[(size_t)k * NPOS + nb + n];
        }
        __syncthreads();
        #pragma unroll
        for (int k = 0; k < 32; ++k) {
            float4 a  = *reinterpret_cast<const float4*>(&Ws[k][o0]);
            float4 xv = *reinterpret_cast<const float4*>(&Xs[k][n0]);
            acc[0][0] += a.x*xv.x; acc[0][1] += a.x*xv.y; acc[0][2] += a.x*xv.z; acc[0][3] += a.x*xv.w;
            acc[1][0] += a.y*xv.x; acc[1][1] += a.y*xv.y; acc[1][2] += a.y*xv.z; acc[1][3] += a.y*xv.w;
            acc[2][0] += a.z*xv.x; acc[2][1] += a.z*xv.y; acc[2][2] += a.z*xv.z; acc[2][3] += a.z*xv.w;
            acc[3][0] += a.w*xv.x; acc[3][1] += a.w*xv.y; acc[3][2] += a.w*xv.z; acc[3][3] += a.w*xv.w;
        }
        __syncthreads();
    }
    #pragma unroll
    for (int oi = 0; oi < 4; ++oi) {
        float bb = bias[ob + o0 + oi];
        float4 r = make_float4(acc[oi][0]+bb, acc[oi][1]+bb, acc[oi][2]+bb, acc[oi][3]+bb);
        *reinterpret_cast<float4*>(&y[((size_t)b * 512 + ob + o0 + oi) * NPOS + nb + n0]) = r;
    }
}

// ---------------------------------------------------------------------------
// BN stats (unchanged)
// ---------------------------------------------------------------------------
__global__ __launch_bounds__(256) void bn_stats_kernel(
    const float* __restrict__ h, const float* __restrict__ gamma,
    const float* __restrict__ beta, float* __restrict__ scale,
    float* __restrict__ shift)
{
    const int ch = blockIdx.x;
    const int tid = threadIdx.x;
    float s = 0.f, s2 = 0.f;
    for (int b = 0; b < BATCH; ++b) {
        const float4* p = reinterpret_cast<const float4*>(h + ((size_t)b * 512 + ch) * NPOS);
        for (int i = tid; i < NPOS / 4; i += 256) {
            float4 v = p[i];
            s  += (v.x + v.y) + (v.z + v.w);
            s2 += v.x*v.x + v.y*v.y + v.z*v.z + v.w*v.w;
        }
    }
    __shared__ float r1[256], r2[256];
    r1[tid] = s; r2[tid] = s2;
    __syncthreads();
    for (int off = 128; off > 0; off >>= 1) {
        if (tid < off) { r1[tid] += r1[tid + off]; r2[tid] += r2[tid + off]; }
        __syncthreads();
    }
    if (tid == 0) {
        const float inv = 1.f / (float)(BATCH * NPOS);
        float mean = r1[0] * inv;
        float var  = r2[0] * inv - mean * mean;
        float rs   = rsqrtf(var + 1e-5f);
        float scv  = gamma[ch] * rs;
        scale[ch] = scv;
        shift[ch] = beta[ch] - mean * scv;
    }
}

// ---------------------------------------------------------------------------
// Final conv + BN + ReLU + residual (unchanged)
// ---------------------------------------------------------------------------
__global__ __launch_bounds__(256) void conv1x1_bnout_kernel(
    const float* __restrict__ h, const float* __restrict__ scale,
    const float* __restrict__ shift, const float* __restrict__ w,
    const float* __restrict__ bias, const float* __restrict__ resid,
    float* __restrict__ y)
{
    __shared__ float Ws[32][68];
    __shared__ float Xs[32][64];
    const int b  = blockIdx.z;
    const int ob = blockIdx.y * 64;
    const int nb = blockIdx.x * 64;
    const int tid = threadIdx.x;
    const int tx = tid & 15, ty = tid >> 4;
    const int n0 = tx * 4, o0 = ty * 4;
    float acc[4][4] = {};
    for (int k0 = 0; k0 < 512; k0 += 32) {
        const float* xb = h + ((size_t)b * 512 + k0) * NPOS;
        {
            int o  = tid >> 2;
            int kk = (tid & 3) * 8;
            const float* wp = w + (size_t)(ob + o) * 512 + k0 + kk;
            #pragma unroll
            for (int i = 0; i < 8; ++i) Ws[kk + i][o] = wp[i];
        }
        #pragma unroll
        for (int i = 0; i < 8; ++i) {
            int idx = tid + i * 256;
            int k = idx >> 6, n = idx & 63;
            float v = xb[(size_t)k * NPOS + nb + n];
            v = fmaf(v, __ldg(&scale[k0 + k]), __ldg(&shift[k0 + k]));
            Xs[k][n] = fmaxf(v, 0.f);
        }
        __syncthreads();
        #pragma unroll
        for (int k = 0; k < 32; ++k) {
            float4 a  = *reinterpret_cast<const float4*>(&Ws[k][o0]);
            float4 xv = *reinterpret_cast<const float4*>(&Xs[k][n0]);
            acc[0][0] += a.x*xv.x; acc[0][1] += a.x*xv.y; acc[0][2] += a.x*xv.z; acc[0][3] += a.x*xv.w;
            acc[1][0] += a.y*xv.x; acc[1][1] += a.y*xv.y; acc[1][2] += a.y*xv.z; acc[1][3] += a.y*xv.w;
            acc[2][0] += a.z*xv.x; acc[2][1] += a.z*xv.y; acc[2][2] += a.z*xv.z; acc[2][3] += a.z*xv.w;
            acc[3][0] += a.w*xv.x; acc[3][1] += a.w*xv.y; acc[3][2] += a.w*xv.z; acc[3][3] += a.w*xv.w;
        }
        __syncthreads();
    }
    #pragma unroll
    for (int oi = 0; oi < 4; ++oi) {
        float bb = bias[ob + o0 + oi];
        const float4 rv = *reinterpret_cast<const float4*>(
            &resid[((size_t)b * 256 + ob + o0 + oi) * NPOS + nb + n0]);
        float4 r = make_float4(acc[oi][0]+bb+rv.x, acc[oi][1]+bb+rv.y,
                               acc[oi][2]+bb+rv.z, acc[oi][3]+bb+rv.w);
        *reinterpret_cast<float4*>(&y[((size_t)b * 256 + ob + o0 + oi) * NPOS + nb + n0]) = r;
    }
}

// ---------------------------------------------------------------------------
extern "C" void kernel_launch(void* const* d_in, const int* in_sizes, int n_in,
                              void* d_out, int out_size)
{
    const float* m1    = (const float*)d_in[0];
    const float* m2    = (const float*)d_in[1];
    const float* wq    = (const float*)d_in[2];
    const float* bq    = (const float*)d_in[3];
    const float* wk    = (const float*)d_in[4];
    const float* bk    = (const float*)d_in[5];
    const float* wv    = (const float*)d_in[6];
    const float* bv    = (const float*)d_in[7];
    const float* wm    = (const float*)d_in[8];
    const float* bm    = (const float*)d_in[9];
    const float* w1    = (const float*)d_in[10];
    const float* b1    = (const float*)d_in[11];
    const float* gamma = (const float*)d_in[12];
    const float* beta  = (const float*)d_in[13];
    const float* w2    = (const float*)d_in[14];
    const float* b2    = (const float*)d_in[15];
    float* out = (float*)d_out;

    float* base = nullptr;
    cudaGetSymbolAddress((void**)&base, g_scratch);
    __nv_bfloat16* Qb = (__nv_bfloat16*)base;                       // SZ bf16
    __nv_bfloat16* Kb = (__nv_bfloat16*)(base + (size_t)SZ / 2);
    __nv_bfloat16* Vb = (__nv_bfloat16*)(base + (size_t)SZ);
    float* O     = base + (size_t)SZ + SZ / 2;
    float* AV    = O + (size_t)SZ;
    float* H     = AV + (size_t)SZ;                                 // 2*SZ
    float* SCALE = H + 2 * (size_t)SZ;
    float* SHIFT = SCALE + 512;

    const int flash_smem = 49152;
    cudaFuncSetAttribute(flash_mma_kernel,
                         cudaFuncAttributeMaxDynamicSharedMemorySize, flash_smem);

    dim3 blk(256);
    const float qscale = 0.125f * 1.4426950408889634f;  // 1/sqrt(64) * log2(e)
    conv1x1_qkv_bf16<<<dim3(64, 4, 8), blk>>>(m1, wq, bq, Qb, qscale);
    conv1x1_qkv_bf16<<<dim3(64, 4, 8), blk>>>(m2, wk, bk, Kb, 1.0f);
    conv1x1_qkv_bf16<<<dim3(64, 4, 8), blk>>>(m2, wv, bv, Vb, 1.0f);
    flash_mma_kernel<<<dim3(32, 4, 8), blk, flash_smem>>>(Qb, Kb, Vb, O);
    conv1x1_kernel<<<dim3(64, 4, 8), blk>>>(O, wm, bm, AV, 256, 256, NPOS);
    conv1x1_cat_kernel<<<dim3(64, 8, 8), blk>>>(m1, AV, w1, b1, H);
    bn_stats_kernel<<<512, blk>>>(H, gamma, beta, SCALE, SHIFT);
    conv1x1_bnout_kernel<<<dim3(64, 4, 8), blk>>>(H, SCALE, SHIFT, w2, b2, m1, out);
}

// round 4
// speedup vs baseline: 4.5554x; 1.7835x over previous
#include <cuda_runtime.h>
#include <cuda_bf16.h>
#include <math.h>
#include <stdint.h>

#define BATCH 8
#define CCH   256
#define NPOS  4096
#define SZ    (BATCH * CCH * NPOS)   // 8,388,608

__device__ float g_scratch[7ull * SZ + 1024];

// ---------------------------------------------------------------------------
// helpers
// ---------------------------------------------------------------------------
__device__ __forceinline__ float fast_exp2(float x) {
    x = fmaxf(x, -126.0f);
    float t = x + 12582912.0f;
    int   i = __float_as_int(t) - 0x4B400000;
    float f = x - (t - 12582912.0f);
    float p =             1.3333558e-3f;
    p = fmaf(p, f, 9.6181291e-3f);
    p = fmaf(p, f, 5.5504109e-2f);
    p = fmaf(p, f, 2.4022651e-1f);
    p = fmaf(p, f, 6.9314718e-1f);
    p = fmaf(p, f, 1.0f);
    return __int_as_float(__float_as_int(p) + (i << 23));
}

__device__ __forceinline__ uint32_t packbf(float lo, float hi) {
    __nv_bfloat162 v = __floats2bfloat162_rn(lo, hi);
    return *reinterpret_cast<uint32_t*>(&v);
}

__device__ __forceinline__ float to_tf32(float x) {
    float r;
    asm("cvt.rna.tf32.f32 %0, %1;\n" : "=f"(r) : "f"(x));
    return r;
}

__device__ __forceinline__ void ldsm4(uint32_t& r0, uint32_t& r1, uint32_t& r2,
                                      uint32_t& r3, uint32_t a) {
    asm volatile("ldmatrix.sync.aligned.m8n8.x4.shared.b16 {%0,%1,%2,%3}, [%4];\n"
                 : "=r"(r0), "=r"(r1), "=r"(r2), "=r"(r3) : "r"(a));
}
__device__ __forceinline__ void ldsm4t(uint32_t& r0, uint32_t& r1, uint32_t& r2,
                                       uint32_t& r3, uint32_t a) {
    asm volatile("ldmatrix.sync.aligned.m8n8.x4.trans.shared.b16 {%0,%1,%2,%3}, [%4];\n"
                 : "=r"(r0), "=r"(r1), "=r"(r2), "=r"(r3) : "r"(a));
}
__device__ __forceinline__ void mma16816(float* d, const uint32_t* a,
                                         uint32_t b0, uint32_t b1) {
    asm volatile("mma.sync.aligned.m16n8k16.row.col.f32.bf16.bf16.f32 "
                 "{%0,%1,%2,%3}, {%4,%5,%6,%7}, {%8,%9}, {%0,%1,%2,%3};\n"
                 : "+f"(d[0]), "+f"(d[1]), "+f"(d[2]), "+f"(d[3])
                 : "r"(a[0]), "r"(a[1]), "r"(a[2]), "r"(a[3]), "r"(b0), "r"(b1));
}
__device__ __forceinline__ void mma_tf32(float* d, const uint32_t* a,
                                         uint32_t b0, uint32_t b1) {
    asm volatile("mma.sync.aligned.m16n8k8.row.col.f32.tf32.tf32.f32 "
                 "{%0,%1,%2,%3}, {%4,%5,%6,%7}, {%8,%9}, {%0,%1,%2,%3};\n"
                 : "+f"(d[0]), "+f"(d[1]), "+f"(d[2]), "+f"(d[3])
                 : "r"(a[0]), "r"(a[1]), "r"(a[2]), "r"(a[3]), "r"(b0), "r"(b1));
}
__device__ __forceinline__ uint32_t swz(uint32_t row, uint32_t chunk) {
    return row * 128u + ((chunk ^ (row & 7u)) * 16u);
}

// ---------------------------------------------------------------------------
// tf32 tensor-core 1x1 conv: Y[b,o,n] = bias[o] + sum_c W[o,c] X[b,c,n]
// Block tile 64o x 128n, K-step 16. 8 warps, warp tile 32o x 32n.
// IN_MODE : 0 plain x1 | 1 concat(x1,x2) | 2 BN(scale,shift)+ReLU on x1
// OUT_MODE: 0 fp32+bias | 1 fp32+bias+resid | 2 bf16 [b,h,n,d] * qscale
// ---------------------------------------------------------------------------
template<int CIN, int IN_MODE, int OUT_MODE>
__global__ __launch_bounds__(256) void conv_tf32_kernel(
    const float* __restrict__ x1, const float* __restrict__ x2,
    const float* __restrict__ w, const float* __restrict__ bias,
    const float* __restrict__ scale, const float* __restrict__ shift,
    const float* __restrict__ resid, float* __restrict__ yf,
    __nv_bfloat16* __restrict__ yb, float qscale, int Cout)
{
    __shared__ float Ws[64 * 20];    // [o][k], stride 20 (conflict-free A frags)
    __shared__ float Xs[16 * 132];   // [k][n], stride 132 (<=2-way B frags)

    const int tid = threadIdx.x;
    const int b  = blockIdx.z;
    const int ob = blockIdx.y * 64;
    const int nb = blockIdx.x * 128;
    const int l = tid & 31, wid = tid >> 5;
    const int wo = (wid & 1) * 32, wn = (wid >> 1) * 32;

    const int lwo = tid >> 2, lwk = (tid & 3) * 4;   // W loader: o, k4
    const int lxk = tid >> 4, lxn = (tid & 15) * 8;  // X loader: k, n8

    float4 wr, xr0, xr1;

    auto gload = [&](int kt) {
        wr = *reinterpret_cast<const float4*>(
            &w[(size_t)(ob + lwo) * CIN + kt * 16 + lwk]);
        const int c = kt * 16 + lxk;
        const float* xp;
        if (IN_MODE == 1) {
            xp = (c < 256) ? &x1[((size_t)b * 256 + c) * NPOS + nb + lxn]
                           : &x2[((size_t)b * 256 + (c - 256)) * NPOS + nb + lxn];
        } else {
            xp = &x1[((size_t)b * CIN + c) * NPOS + nb + lxn];
        }
        xr0 = *reinterpret_cast<const float4*>(xp);
        xr1 = *reinterpret_cast<const float4*>(xp + 4);
        if (IN_MODE == 2) {
            const float sc = __ldg(&scale[c]), sh = __ldg(&shift[c]);
            xr0.x = fmaxf(fmaf(xr0.x, sc, sh), 0.f);
            xr0.y = fmaxf(fmaf(xr0.y, sc, sh), 0.f);
            xr0.z = fmaxf(fmaf(xr0.z, sc, sh), 0.f);
            xr0.w = fmaxf(fmaf(xr0.w, sc, sh), 0.f);
            xr1.x = fmaxf(fmaf(xr1.x, sc, sh), 0.f);
            xr1.y = fmaxf(fmaf(xr1.y, sc, sh), 0.f);
            xr1.z = fmaxf(fmaf(xr1.z, sc, sh), 0.f);
            xr1.w = fmaxf(fmaf(xr1.w, sc, sh), 0.f);
        }
    };
    auto sts = [&]() {
        float* wp = &Ws[lwo * 20 + lwk];
        wp[0] = to_tf32(wr.x); wp[1] = to_tf32(wr.y);
        wp[2] = to_tf32(wr.z); wp[3] = to_tf32(wr.w);
        float* xp = &Xs[lxk * 132 + lxn];
        xp[0] = to_tf32(xr0.x); xp[1] = to_tf32(xr0.y);
        xp[2] = to_tf32(xr0.z); xp[3] = to_tf32(xr0.w);
        xp[4] = to_tf32(xr1.x); xp[5] = to_tf32(xr1.y);
        xp[6] = to_tf32(xr1.z); xp[7] = to_tf32(xr1.w);
    };

    float acc[2][4][4] = {};
    const int nk = CIN / 16;
    gload(0);
    for (int kt = 0; kt < nk; ++kt) {
        sts();
        __syncthreads();
        if (kt + 1 < nk) gload(kt + 1);
        #pragma unroll
        for (int k8 = 0; k8 < 16; k8 += 8) {
            uint32_t a[2][4], bf[4][2];
            #pragma unroll
            for (int i = 0; i < 2; ++i) {
                const int row = wo + i * 16 + (l >> 2);
                const int kc = k8 + (l & 3);
                a[i][0] = __float_as_uint(Ws[row * 20 + kc]);
                a[i][1] = __float_as_uint(Ws[(row + 8) * 20 + kc]);
                a[i][2] = __float_as_uint(Ws[row * 20 + kc + 4]);
                a[i][3] = __float_as_uint(Ws[(row + 8) * 20 + kc + 4]);
            }
            #pragma unroll
            for (int j = 0; j < 4; ++j) {
                const int col = wn + j * 8 + (l >> 2);
                const int kr = k8 + (l & 3);
                bf[j][0] = __float_as_uint(Xs[kr * 132 + col]);
                bf[j][1] = __float_as_uint(Xs[(kr + 4) * 132 + col]);
            }
            #pragma unroll
            for (int i = 0; i < 2; ++i)
                #pragma unroll
                for (int j = 0; j < 4; ++j)
                    mma_tf32(acc[i][j], a[i], bf[j][0], bf[j][1]);
        }
        __syncthreads();
    }

    // epilogue
    #pragma unroll
    for (int i = 0; i < 2; ++i) {
        const int r0 = ob + wo + i * 16 + (l >> 2);
        const int r1 = r0 + 8;
        const float bi0 = bias[r0], bi1 = bias[r1];
        #pragma unroll
        for (int j = 0; j < 4; ++j) {
            const int n = nb + wn + j * 8 + 2 * (l & 3);
            float c0 = acc[i][j][0] + bi0, c1 = acc[i][j][1] + bi0;
            float c2 = acc[i][j][2] + bi1, c3 = acc[i][j][3] + bi1;
            if (OUT_MODE == 2) {
                const int h0 = r0 >> 6, d0 = r0 & 63;
                const int h1 = r1 >> 6, d1 = r1 & 63;
                size_t i0 = (((size_t)(b * 4 + h0)) * NPOS + n) * 64 + d0;
                size_t i1 = (((size_t)(b * 4 + h1)) * NPOS + n) * 64 + d1;
                yb[i0]      = __float2bfloat16(c0 * qscale);
                yb[i0 + 64] = __float2bfloat16(c1 * qscale);
                yb[i1]      = __float2bfloat16(c2 * qscale);
                yb[i1 + 64] = __float2bfloat16(c3 * qscale);
            } else {
                size_t i0 = ((size_t)b * Cout + r0) * NPOS + n;
                size_t i1 = ((size_t)b * Cout + r1) * NPOS + n;
                if (OUT_MODE == 1) {
                    float2 rv0 = *reinterpret_cast<const float2*>(&resid[i0]);
                    float2 rv1 = *reinterpret_cast<const float2*>(&resid[i1]);
                    c0 += rv0.x; c1 += rv0.y; c2 += rv1.x; c3 += rv1.y;
                }
                *reinterpret_cast<float2*>(&yf[i0]) = make_float2(c0, c1);
                *reinterpret_cast<float2*>(&yf[i1]) = make_float2(c2, c3);
            }
        }
    }
}

// ---------------------------------------------------------------------------
// Flash attention (unchanged from R2)
// ---------------------------------------------------------------------------
__global__ __launch_bounds__(256, 2) void flash_mma_kernel(
    const __nv_bfloat16* __restrict__ Qb, const __nv_bfloat16* __restrict__ Kb,
    const __nv_bfloat16* __restrict__ Vb, float* __restrict__ O)
{
    extern __shared__ char smc[];
    const int tid = threadIdx.x;
    const int w = tid >> 5, l = tid & 31;
    const int b = blockIdx.z, h = blockIdx.y;
    const int nb = blockIdx.x * 128;
    const size_t headbase = ((size_t)(b * 4 + h)) * NPOS * 64;

    const uint32_t smem_base = (uint32_t)__cvta_generic_to_shared(smc);
    const uint32_t qs_b = smem_base;

    #pragma unroll
    for (int i = 0; i < 4; ++i) {
        int idx = tid + i * 256;
        int r = idx >> 3, c = idx & 7;
        const int4* src = reinterpret_cast<const int4*>(
            Qb + headbase + (size_t)(nb + r) * 64 + c * 8);
        *reinterpret_cast<int4*>(smc + swz(r, c)) = *src;
    }

    auto load_tile = [&](int mb, int s) {
        uint32_t kbase = smem_base + 16384 + s * 16384;
        uint32_t vbase = kbase + 8192;
        #pragma unroll
        for (int i = 0; i < 2; ++i) {
            int idx = tid + i * 256;
            int r = idx >> 3, c = idx & 7;
            const __nv_bfloat16* ksrc = Kb + headbase + (size_t)(mb + r) * 64 + c * 8;
            const __nv_bfloat16* vsrc = Vb + headbase + (size_t)(mb + r) * 64 + c * 8;
            uint32_t o = swz(r, c);
            asm volatile("cp.async.cg.shared.global [%0], [%1], 16;\n"
                         :: "r"(kbase + o), "l"(ksrc));
            asm volatile("cp.async.cg.shared.global [%0], [%1], 16;\n"
                         :: "r"(vbase + o), "l"(vsrc));
        }
        asm volatile("cp.async.commit_group;\n");
    };
    load_tile(0, 0);

    float oacc[8][4] = {};
    float mA = -10000.f, mB = -10000.f, lA = 0.f, lB = 0.f;
    const int m0q = w * 16;
    const uint32_t arow = m0q + (l & 15);
    const uint32_t achk = (uint32_t)(l >> 4);
    const uint32_t brow8 = (l & 7) + ((l & 16) >> 1);
    const uint32_t bchk = (uint32_t)((l >> 3) & 1);

    for (int it = 0; it < NPOS / 64; ++it) {
        if (it + 1 < NPOS / 64) {
            load_tile((it + 1) * 64, (it + 1) & 1);
            asm volatile("cp.async.wait_group 1;\n");
        } else {
            asm volatile("cp.async.wait_group 0;\n");
        }
        __syncthreads();
        const uint32_t kb = smem_base + 16384 + (it & 1) * 16384;
        const uint32_t vb = kb + 8192;

        float sacc[8][4] = {};
        #pragma unroll
        for (int kk = 0; kk < 4; ++kk) {
            uint32_t af[4];
            ldsm4(af[0], af[1], af[2], af[3], qs_b + swz(arow, kk * 2 + achk));
            #pragma unroll
            for (int jj = 0; jj < 4; ++jj) {
                uint32_t b0, b1, b2, b3;
                ldsm4(b0, b1, b2, b3, kb + swz(jj * 16 + brow8, kk * 2 + bchk));
                mma16816(sacc[2 * jj], af, b0, b1);
                mma16816(sacc[2 * jj + 1], af, b2, b3);
            }
        }

        float rmA = -1e30f, rmB = -1e30f;
        #pragma unroll
        for (int j = 0; j < 8; ++j) {
            rmA = fmaxf(rmA, fmaxf(sacc[j][0], sacc[j][1]));
            rmB = fmaxf(rmB, fmaxf(sacc[j][2], sacc[j][3]));
        }
        rmA = fmaxf(rmA, __shfl_xor_sync(0xffffffffu, rmA, 1));
        rmA = fmaxf(rmA, __shfl_xor_sync(0xffffffffu, rmA, 2));
        rmB = fmaxf(rmB, __shfl_xor_sync(0xffffffffu, rmB, 1));
        rmB = fmaxf(rmB, __shfl_xor_sync(0xffffffffu, rmB, 2));
        const float mnA = fmaxf(mA, rmA), mnB = fmaxf(mB, rmB);
        const float aA = fast_exp2(mA - mnA), aB = fast_exp2(mB - mnB);
        mA = mnA; mB = mnB;
        float psA = 0.f, psB = 0.f;
        #pragma unroll
        for (int j = 0; j < 8; ++j) {
            sacc[j][0] = fast_exp2(sacc[j][0] - mnA);
            sacc[j][1] = fast_exp2(sacc[j][1] - mnA);
            sacc[j][2] = fast_exp2(sacc[j][2] - mnB);
            sacc[j][3] = fast_exp2(sacc[j][3] - mnB);
            psA += sacc[j][0] + sacc[j][1];
            psB += sacc[j][2] + sacc[j][3];
        }
        psA += __shfl_xor_sync(0xffffffffu, psA, 1);
        psA += __shfl_xor_sync(0xffffffffu, psA, 2);
        psB += __shfl_xor_sync(0xffffffffu, psB, 1);
        psB += __shfl_xor_sync(0xffffffffu, psB, 2);
        lA = lA * aA + psA;
        lB = lB * aB + psB;
        #pragma unroll
        for (int j = 0; j < 8; ++j) {
            oacc[j][0] *= aA; oacc[j][1] *= aA;
            oacc[j][2] *= aB; oacc[j][3] *= aB;
        }

        #pragma unroll
        for (int kk = 0; kk < 4; ++kk) {
            uint32_t pa[4];
            pa[0] = packbf(sacc[2*kk][0],   sacc[2*kk][1]);
            pa[1] = packbf(sacc[2*kk][2],   sacc[2*kk][3]);
            pa[2] = packbf(sacc[2*kk+1][0], sacc[2*kk+1][1]);
            pa[3] = packbf(sacc[2*kk+1][2], sacc[2*kk+1][3]);
            const uint32_t vrow = kk * 16 + (l & 15);
            #pragma unroll
            for (int jj = 0; jj < 4; ++jj) {
                uint32_t b0, b1, b2, b3;
                ldsm4t(b0, b1, b2, b3, vb + swz(vrow, jj * 2 + achk));
                mma16816(oacc[2 * jj], pa, b0, b1);
                mma16816(oacc[2 * jj + 1], pa, b2, b3);
            }
        }
        __syncthreads();
    }

    const float ilA = 1.f / lA, ilB = 1.f / lB;
    const int rA = nb + m0q + (l >> 2), rB = rA + 8;
    const size_t obase = ((size_t)b * CCH + h * 64) * NPOS;
    #pragma unroll
    for (int j = 0; j < 8; ++j) {
        int d0 = j * 8 + (l & 3) * 2;
        O[obase + (size_t)d0 * NPOS + rA]       = oacc[j][0] * ilA;
        O[obase + (size_t)(d0 + 1) * NPOS + rA] = oacc[j][1] * ilA;
        O[obase + (size_t)d0 * NPOS + rB]       = oacc[j][2] * ilB;
        O[obase + (size_t)(d0 + 1) * NPOS + rB] = oacc[j][3] * ilB;
    }
}

// ---------------------------------------------------------------------------
// BN stats (unchanged)
// ---------------------------------------------------------------------------
__global__ __launch_bounds__(256) void bn_stats_kernel(
    const float* __restrict__ h, const float* __restrict__ gamma,
    const float* __restrict__ beta, float* __restrict__ scale,
    float* __restrict__ shift)
{
    const int ch = blockIdx.x;
    const int tid = threadIdx.x;
    float s = 0.f, s2 = 0.f;
    for (int b = 0; b < BATCH; ++b) {
        const float4* p = reinterpret_cast<const float4*>(h + ((size_t)b * 512 + ch) * NPOS);
        for (int i = tid; i < NPOS / 4; i += 256) {
            float4 v = p[i];
            s  += (v.x + v.y) + (v.z + v.w);
            s2 += v.x*v.x + v.y*v.y + v.z*v.z + v.w*v.w;
        }
    }
    __shared__ float r1[256], r2[256];
    r1[tid] = s; r2[tid] = s2;
    __syncthreads();
    for (int off = 128; off > 0; off >>= 1) {
        if (tid < off) { r1[tid] += r1[tid + off]; r2[tid] += r2[tid + off]; }
        __syncthreads();
    }
    if (tid == 0) {
        const float inv = 1.f / (float)(BATCH * NPOS);
        float mean = r1[0] * inv;
        float var  = r2[0] * inv - mean * mean;
        float rs   = rsqrtf(var + 1e-5f);
        float scv  = gamma[ch] * rs;
        scale[ch] = scv;
        shift[ch] = beta[ch] - mean * scv;
    }
}

// ---------------------------------------------------------------------------
extern "C" void kernel_launch(void* const* d_in, const int* in_sizes, int n_in,
                              void* d_out, int out_size)
{
    const float* m1    = (const float*)d_in[0];
    const float* m2    = (const float*)d_in[1];
    const float* wq    = (const float*)d_in[2];
    const float* bq    = (const float*)d_in[3];
    const float* wk    = (const float*)d_in[4];
    const float* bk    = (const float*)d_in[5];
    const float* wv    = (const float*)d_in[6];
    const float* bv    = (const float*)d_in[7];
    const float* wm    = (const float*)d_in[8];
    const float* bm    = (const float*)d_in[9];
    const float* w1    = (const float*)d_in[10];
    const float* b1    = (const float*)d_in[11];
    const float* gamma = (const float*)d_in[12];
    const float* beta  = (const float*)d_in[13];
    const float* w2    = (const float*)d_in[14];
    const float* b2    = (const float*)d_in[15];
    float* out = (float*)d_out;

    float* base = nullptr;
    cudaGetSymbolAddress((void**)&base, g_scratch);
    __nv_bfloat16* Qb = (__nv_bfloat16*)base;
    __nv_bfloat16* Kb = (__nv_bfloat16*)(base + (size_t)SZ / 2);
    __nv_bfloat16* Vb = (__nv_bfloat16*)(base + (size_t)SZ);
    float* O     = base + (size_t)SZ + SZ / 2;
    float* AV    = O + (size_t)SZ;
    float* H     = AV + (size_t)SZ;
    float* SCALE = H + 2 * (size_t)SZ;
    float* SHIFT = SCALE + 512;

    const int flash_smem = 49152;
    cudaFuncSetAttribute(flash_mma_kernel,
                         cudaFuncAttributeMaxDynamicSharedMemorySize, flash_smem);

    dim3 blk(256);
    const float qscale = 0.125f * 1.4426950408889634f;

    // QKV: tf32 GEMM -> bf16 [b,h,n,d]
    conv_tf32_kernel<256,0,2><<<dim3(32,4,8), blk>>>(
        m1, nullptr, wq, bq, nullptr, nullptr, nullptr, nullptr, Qb, qscale, 256);
    conv_tf32_kernel<256,0,2><<<dim3(32,4,8), blk>>>(
        m2, nullptr, wk, bk, nullptr, nullptr, nullptr, nullptr, Kb, 1.0f, 256);
    conv_tf32_kernel<256,0,2><<<dim3(32,4,8), blk>>>(
        m2, nullptr, wv, bv, nullptr, nullptr, nullptr, nullptr, Vb, 1.0f, 256);

    flash_mma_kernel<<<dim3(32,4,8), blk, flash_smem>>>(Qb, Kb, Vb, O);

    // wm projection: fp32 out
    conv_tf32_kernel<256,0,0><<<dim3(32,4,8), blk>>>(
        O, nullptr, wm, bm, nullptr, nullptr, nullptr, AV, nullptr, 1.0f, 256);
    // cat conv -> H (512 ch)
    conv_tf32_kernel<512,1,0><<<dim3(32,8,8), blk>>>(
        m1, AV, w1, b1, nullptr, nullptr, nullptr, H, nullptr, 1.0f, 512);
    bn_stats_kernel<<<512, blk>>>(H, gamma, beta, SCALE, SHIFT);
    // final conv with BN+ReLU input transform + residual
    conv_tf32_kernel<512,2,1><<<dim3(32,4,8), blk>>>(
        H, nullptr, w2, b2, SCALE, SHIFT, m1, out, nullptr, 1.0f, 256);
}